// round 1
// baseline (speedup 1.0000x reference)
#include <cuda_runtime.h>

// DecisionGate: g = 1/(1+|x|^4); mask = g>=0.5; dispatched[b,p,:] = (mask? g:0)*act[b,:]
// Shapes: x [4096,64] f32, act [4096,512] f32, batch_inds [4096] i64 (unused by outputs)
// Output layout (f32, concatenated): g [B*P] | mask [B*P] | dispatched [B*P*D]

#define B_DIM 4096
#define P_DIM 64
#define D_DIM 512

__global__ __launch_bounds__(128, 16)
void decision_gate_kernel(const float* __restrict__ x,
                          const float* __restrict__ act,
                          float* __restrict__ out) {
    const int tile = blockIdx.x;          // tile = b * P_DIM + p
    const int b = tile >> 6;              // P_DIM = 64

    // Gate math (uniform across block; single broadcast load, L1-resident)
    const float xv = __ldg(&x[tile]);
    const float x2 = xv * xv;
    const float g  = 1.0f / (1.0f + x2 * x2);
    const bool  m  = (g >= 0.5f);
    const float w  = m ? g : 0.0f;

    if (threadIdx.x == 0) {
        out[tile] = g;
        out[(size_t)B_DIM * P_DIM + tile] = m ? 1.0f : 0.0f;
    }

    // dispatched[b,p,:] = w * act[b,:]  (512 floats = 128 threads x float4)
    const float4* __restrict__ a4 =
        reinterpret_cast<const float4*>(act + (size_t)b * D_DIM);
    float4* __restrict__ o4 =
        reinterpret_cast<float4*>(out + (size_t)2 * B_DIM * P_DIM
                                      + (size_t)tile * D_DIM);

    float4 v = a4[threadIdx.x];
    float4 r;
    r.x = v.x * w;
    r.y = v.y * w;
    r.z = v.z * w;
    r.w = v.w * w;
    o4[threadIdx.x] = r;
}

extern "C" void kernel_launch(void* const* d_in, const int* in_sizes, int n_in,
                              void* d_out, int out_size) {
    const float* x   = (const float*)d_in[0];   // [4096, 64]
    const float* act = (const float*)d_in[1];   // [4096, 512]
    // d_in[2] = batch_inds (int64) — not needed for the dense outputs
    float* out = (float*)d_out;

    const int n_tiles = B_DIM * P_DIM;          // 262144 CTAs
    decision_gate_kernel<<<n_tiles, 128>>>(x, act, out);
}

// round 2
// speedup vs baseline: 1.9164x; 1.9164x over previous
#include <cuda_runtime.h>

// DecisionGate: g = 1/(1+|x|^4); mask = g>=0.5; dispatched[b,p,:] = (mask? g:0)*act[b,:]
// x [4096,64] f32, act [4096,512] f32. Output f32: g [B*P] | mask [B*P] | dispatched [B*P*D]

#define B_DIM 4096
#define P_DIM 64
#define D_DIM 512
#define BP    (B_DIM * P_DIM)

__global__ __launch_bounds__(128, 16)
void decision_gate_kernel(const float* __restrict__ x,
                          const float* __restrict__ act,
                          float* __restrict__ out) {
    const int b = blockIdx.x;
    const int t = threadIdx.x;            // 0..127, one float4 of D=512 each

    // Each thread owns one float4 of act[b] for the whole CTA lifetime.
    const float4 v = reinterpret_cast<const float4*>(act + (size_t)b * D_DIM)[t];

    // Threads 0..63 compute the 64 gate values; emit g and mask; stash w in smem.
    __shared__ float wsm[P_DIM];
    if (t < P_DIM) {
        const float xv = x[b * P_DIM + t];
        const float x2 = xv * xv;
        const float g  = 1.0f / (1.0f + x2 * x2);
        const bool  m  = (g >= 0.5f);
        out[b * P_DIM + t]      = g;
        out[BP + b * P_DIM + t] = m ? 1.0f : 0.0f;
        wsm[t] = m ? g : 0.0f;
    }
    __syncthreads();

    // 64 independent streaming stores per thread: dispatched[b,p,:] = w[p] * v
    float4* __restrict__ base =
        reinterpret_cast<float4*>(out + (size_t)2 * BP + (size_t)b * P_DIM * D_DIM) + t;

    #pragma unroll
    for (int p = 0; p < P_DIM; p++) {
        const float w = wsm[p];           // broadcast LDS, conflict-free
        float4 r;
        r.x = v.x * w;
        r.y = v.y * w;
        r.z = v.z * w;
        r.w = v.w * w;
        __stcs(base + (size_t)p * (D_DIM / 4), r);
    }
}

extern "C" void kernel_launch(void* const* d_in, const int* in_sizes, int n_in,
                              void* d_out, int out_size) {
    const float* x   = (const float*)d_in[0];   // [4096, 64]
    const float* act = (const float*)d_in[1];   // [4096, 512]
    float* out = (float*)d_out;

    decision_gate_kernel<<<B_DIM, 128>>>(x, act, out);
}